// round 17
// baseline (speedup 1.0000x reference)
#include <cuda_runtime.h>
#include <cuda_fp16.h>
#include <cstdint>

// ============================================================================
// SwapTestAttention on GB300 — Round 16: tensor-core epilogue (P@V GEMM).
//   R15 flat 2-wave decomposition kept. New: the exp-weights are packed from
//   the QK^T accumulator fragments (C-layout == A-layout) and fed to a second
//   m16n8k16 GEMM against V^T[32k x 8] (6 comps + ones column -> den free).
//   Scalar epilogue ~290 issues -> ~124; vacc 28 regs -> 8; flush = plain STG.
// ============================================================================

#define NTOK 8192
#define NQB  6
#define DIM  64
#define NL   2

#define QT   128                 // queries per qtile (A tile rows)
#define KT   64                  // keys per tile
#define NQT  (NTOK / QT)         // 64 qtiles
#define NKT  (NTOK / KT)         // 128 ktiles
#define NT_TOTAL (NQT * NKT)     // 8192 flat tile-units
#define NCTA 608                 // 2 waves x 2 CTAs/SM x 152 SMs
#define NSLOT 24                 // <=12 covering CTAs x 2 n-warps
#define VSTRIDE 66               // half stride of V^T rows (conflict pad)

// smem byte offsets
#define AH_BYTES  (8 * QT * 16 * 2)          // 32768: A chunks [8][128][16] half
#define BH_BYTES  (8 * KT * 16 * 2)          // 16384 per buffer
#define BH_OFF    AH_BYTES                   // two buffers: 32768 total
#define VS_OFF    (AH_BYTES + 2 * BH_BYTES)  // V^T half [2][8][VSTRIDE]
#define VS_HALVES (8 * VSTRIDE)              // 528 halves per buffer
#define SMEM_BYTES (VS_OFF + 2 * VS_HALVES * 2)   // 67648

// Scratch (device globals; no allocation allowed)
__device__ __half2 g_Qh[NTOK * DIM];         // [token][64] (re,im)
__device__ __half2 g_Kh[NTOK * DIM];
__device__ float   g_V[NTOK * 8];            // 6 used + pad
__device__ float   g_part[NTOK][NSLOT][8];   // token-major partials (6 acc + den + pad)
__device__ float   g_trig[3 * NL * NQB * 2 * 2];  // [role][l][q][gate][{s,c}]

__device__ __forceinline__ float shfl_x(float v, int m) {
    return __shfl_xor_sync(0xffffffffu, v, m);
}
__device__ __forceinline__ void mma_f16(float d[4],
    uint32_t a0, uint32_t a1, uint32_t a2, uint32_t a3,
    uint32_t b0, uint32_t b1)
{
    asm volatile(
        "mma.sync.aligned.m16n8k16.row.col.f32.f16.f16.f32 "
        "{%0,%1,%2,%3}, {%4,%5,%6,%7}, {%8,%9}, {%0,%1,%2,%3};"
        : "+f"(d[0]), "+f"(d[1]), "+f"(d[2]), "+f"(d[3])
        : "r"(a0), "r"(a1), "r"(a2), "r"(a3), "r"(b0), "r"(b1));
}
__device__ __forceinline__ int kperm_pair(int j) {   // position of col 2j
    return 4 * (j & 3) + 2 * (j >> 2);
}
__device__ __forceinline__ uint32_t packw(float a, float b) {
    __half2 h = __floats2half2_rn(a, b);
    return *(uint32_t*)&h;
}
// CTA owning flat tile T (inverse of t0(c) = floor(c*NT_TOTAL/NCTA))
__device__ __forceinline__ int cta_of_tile(int T) {
    return (int)(((long long)(T + 1) * NCTA - 1) / NT_TOTAL);
}

// ---------------------------------------------------------------------------
// Phase 0a: precompute sin/cos of all 72 param gate half-angles (3 roles).
// ---------------------------------------------------------------------------
__global__ void trig_kernel(const float* __restrict__ pq,
                            const float* __restrict__ pk,
                            const float* __restrict__ pv)
{
    int t = threadIdx.x;
    if (t >= 3 * NL * NQB * 2) return;
    int role = t / (NL * NQB * 2);
    int g    = t - role * (NL * NQB * 2);
    const float* p = (role == 0) ? pq : (role == 1) ? pk : pv;
    float s, c; __sincosf(0.5f * p[g], &s, &c);
    g_trig[t * 2 + 0] = s;
    g_trig[t * 2 + 1] = c;
}

// Phase 0b: zero the partials table (slots not covered stay zero).
__global__ void zero_kernel()
{
    float4* p = (float4*)g_part;
    int i = blockIdx.x * 256 + threadIdx.x;
    if (i < NTOK * NSLOT * 2) p[i] = make_float4(0.f, 0.f, 0.f, 0.f);
}

// ---------------------------------------------------------------------------
// Phase 1: one warp simulates one (token, role) circuit.
// ---------------------------------------------------------------------------
__global__ void __launch_bounds__(256) prep_kernel(
    const float* __restrict__ x)
{
    int gw    = (blockIdx.x * 256 + threadIdx.x) >> 5;
    int lane  = threadIdx.x & 31;
    int token = gw & (NTOK - 1);
    int role  = gw >> 13;                  // 0=Q, 1=K, 2=V
    const float* tg = g_trig + role * (NL * NQB * 2 * 2);

    float r0 = (lane == 0) ? 1.f : 0.f, i0 = 0.f, r1 = 0.f, i1 = 0.f;

    auto RYsc = [&](float s, float c, int q) {
        if (q == 0) {
            float nr0 = c*r0 - s*r1, ni0 = c*i0 - s*i1;
            float nr1 = s*r0 + c*r1, ni1 = s*i0 + c*i1;
            r0 = nr0; i0 = ni0; r1 = nr1; i1 = ni1;
        } else {
            int m = 1 << (5 - q);
            float pr0 = shfl_x(r0, m), pi0 = shfl_x(i0, m);
            float pr1 = shfl_x(r1, m), pi1 = shfl_x(i1, m);
            float sg = (lane & m) ? s : -s;
            r0 = fmaf(sg, pr0, c*r0); i0 = fmaf(sg, pi0, c*i0);
            r1 = fmaf(sg, pr1, c*r1); i1 = fmaf(sg, pi1, c*i1);
        }
    };
    auto RZsc = [&](float s, float c, int q) {
        if (q == 0) {
            float nr0 = r0*c + i0*s, ni0 = i0*c - r0*s;
            float nr1 = r1*c - i1*s, ni1 = i1*c + r1*s;
            r0 = nr0; i0 = ni0; r1 = nr1; i1 = ni1;
        } else {
            int m = 1 << (5 - q);
            float sg = (lane & m) ? s : -s;
            float nr0 = r0*c - i0*sg, ni0 = i0*c + r0*sg;
            float nr1 = r1*c - i1*sg, ni1 = i1*c + r1*sg;
            r0 = nr0; i0 = ni0; r1 = nr1; i1 = ni1;
        }
    };

    #pragma unroll
    for (int q = 0; q < NQB; q++) {
        float s, c; __sincosf(0.5f * x[token * NQB + q], &s, &c);
        RYsc(s, c, q);
    }

    #pragma unroll
    for (int l = 0; l < NL; l++) {
        #pragma unroll
        for (int q = 0; q < NQB; q++) {
            int base = ((l * NQB + q) * 2) * 2;
            RYsc(tg[base + 0], tg[base + 1], q);
            RZsc(tg[base + 2], tg[base + 3], q);
        }
        r1 = shfl_x(r1, 16); i1 = shfl_x(i1, 16);
        #pragma unroll
        for (int q = 1; q <= 4; q++) {
            int cm = 1 << (5 - q), tm = 1 << (4 - q);
            float t;
            t = shfl_x(r0, tm); if (lane & cm) r0 = t;
            t = shfl_x(i0, tm); if (lane & cm) i0 = t;
            t = shfl_x(r1, tm); if (lane & cm) r1 = t;
            t = shfl_x(i1, tm); if (lane & cm) i1 = t;
        }
        if (lane & 1) { float t = r0; r0 = r1; r1 = t; t = i0; i0 = i1; i1 = t; }
    }

    if (role < 2) {
        __half2* buf = (role == 0) ? g_Qh : g_Kh;
        buf[token * DIM + lane]      = __floats2half2_rn(r0, i0);
        buf[token * DIM + 32 + lane] = __floats2half2_rn(r1, i1);
    } else {
        float p0 = r0*r0 + i0*i0;
        float p1 = r1*r1 + i1*i1;
        float v[6];
        v[0] = p0 - p1;
        #pragma unroll
        for (int q = 1; q < 6; q++) {
            float sgn = ((lane >> (5 - q)) & 1) ? -1.f : 1.f;
            v[q] = sgn * (p0 + p1);
        }
        #pragma unroll
        for (int off = 16; off >= 1; off >>= 1) {
            #pragma unroll
            for (int q = 0; q < 6; q++) v[q] += __shfl_down_sync(0xffffffffu, v[q], off);
        }
        if (lane == 0) {
            #pragma unroll
            for (int q = 0; q < 6; q++) g_V[token * 8 + q] = v[q];
            g_V[token * 8 + 6] = 0.f;
            g_V[token * 8 + 7] = 0.f;
        }
    }
}

// ---------------------------------------------------------------------------
// Phase 2: fp16 m16n8k16 fused attention; epilogue = second GEMM (P@V^T).
// ---------------------------------------------------------------------------
__global__ void __launch_bounds__(256, 2) attn_kernel()
{
    extern __shared__ char smem[];
    __half* Ah = (__half*)smem;                 // [8][QT][16]
    __half* Vh = (__half*)(smem + VS_OFF);      // [2][8][VSTRIDE]

    int tid   = threadIdx.x;
    int lane  = tid & 31;
    int wid   = tid >> 5;
    int warpm = wid & 3;
    int warpn = wid >> 2;
    int rr    = lane >> 2;       // 0..7
    int cc    = lane & 3;        // 0..3
    int c     = blockIdx.x;

    int t0 = (int)(((long long)c * NT_TOTAL) / NCTA);
    int t1 = (int)(((long long)(c + 1) * NT_TOTAL) / NCTA);
    int qt = t0 >> 7;            // current qtile
    int mrow0 = warpm * 32;

    // ---- A tile loader (Q) ----
    auto load_A = [&](int q) {
        const uint2* Qg = (const uint2*)(g_Qh + (size_t)(q * QT) * DIM);
        for (int idx = tid; idx < QT * 32; idx += 256) {
            int r = idx >> 5, j = idx & 31;               // dims 2j, 2j+1
            uint2 v = Qg[idx];
            uint32_t rep = __byte_perm(v.x, v.y, 0x5410);
            uint32_t imp = __byte_perm(v.x, v.y, 0x7632);
            int kk = j >> 3, p = kperm_pair(j & 7);
            *(uint32_t*)(Ah + (kk * QT + r) * 16 + p)       = rep;
            *(uint32_t*)(Ah + ((kk + 4) * QT + r) * 16 + p) = imp;
        }
    };
    // ---- V^T store into buffer (tid<128: one float4 = half a key's comps) --
    auto store_V = [&](__half* Vb, float4 v, int t128) {
        int key = t128 >> 1;
        if ((t128 & 1) == 0) {
            Vb[0 * VSTRIDE + key] = __float2half(v.x);
            Vb[1 * VSTRIDE + key] = __float2half(v.y);
            Vb[2 * VSTRIDE + key] = __float2half(v.z);
            Vb[3 * VSTRIDE + key] = __float2half(v.w);
        } else {
            Vb[4 * VSTRIDE + key] = __float2half(v.x);
            Vb[5 * VSTRIDE + key] = __float2half(v.y);
            Vb[6 * VSTRIDE + key] = __float2half(1.0f);   // ones column -> den
            Vb[7 * VSTRIDE + key] = __float2half(0.0f);
        }
    };

    // ---- prologue: A tile, first B tile + V^T tile (buffer 0) ----
    load_A(qt);
    {
        int key0 = (t0 & 127) * KT;
        __half* B0 = (__half*)(smem + BH_OFF);
        const uint2* Kg = (const uint2*)(g_Kh + (size_t)key0 * DIM);
        for (int idx = tid; idx < KT * 32; idx += 256) {
            int k = idx >> 5, j = idx & 31;
            uint2 v = Kg[idx];
            uint32_t rep = __byte_perm(v.x, v.y, 0x5410);
            uint32_t imp = __byte_perm(v.x, v.y, 0x7632);
            int kk = j >> 3, p = kperm_pair(j & 7);
            *(uint32_t*)(B0 + (kk * KT + k) * 16 + p)       = rep;
            *(uint32_t*)(B0 + ((kk + 4) * KT + k) * 16 + p) = imp;
        }
        if (tid < 128) {
            float4 v = ((const float4*)(g_V + (size_t)key0 * 8))[tid];
            store_V(Vh, v, tid);
        }
    }
    __syncthreads();

    // persistent output fragments: [mf][4] = (6 comps + den + pad) x 2 q-rows
    float ovac[2][4];
    #pragma unroll
    for (int mf = 0; mf < 2; mf++)
        #pragma unroll
        for (int e = 0; e < 4; e++) ovac[mf][e] = 0.f;

    // ---- flush output fragments for qtile q into g_part, then reset ----
    auto flush = [&](int q) {
        int slot = (c - cta_of_tile(q * 128)) * 2 + warpn;
        #pragma unroll
        for (int mf = 0; mf < 2; mf++) {
            int qi = q * QT + mrow0 + mf * 16 + rr;
            *(float2*)&g_part[qi][slot][2 * cc]     = make_float2(ovac[mf][0], ovac[mf][1]);
            *(float2*)&g_part[qi + 8][slot][2 * cc] = make_float2(ovac[mf][2], ovac[mf][3]);
            ovac[mf][0] = 0.f; ovac[mf][1] = 0.f; ovac[mf][2] = 0.f; ovac[mf][3] = 0.f;
        }
    };

    for (int t = t0; t < t1; t++) {
        int buf = (t - t0) & 1;
        __half* Bh = (__half*)(smem + BH_OFF + buf * BH_BYTES);
        bool has_next = (t + 1 < t1);

        // ---- prefetch next tile's K + V into registers ----
        uint2 kreg[8];
        float4 vreg;
        if (has_next) {
            int key0n = ((t + 1) & 127) * KT;
            const uint2* Kg = (const uint2*)(g_Kh + (size_t)key0n * DIM);
            #pragma unroll
            for (int i = 0; i < 8; i++) kreg[i] = Kg[tid + i * 256];
            if (tid < 128)
                vreg = ((const float4*)(g_V + (size_t)key0n * 8))[tid];
        }

        float re[2][4][4], im[2][4][4];
        #pragma unroll
        for (int mf = 0; mf < 2; mf++)
            #pragma unroll
            for (int nf = 0; nf < 4; nf++)
                #pragma unroll
                for (int e = 0; e < 4; e++) { re[mf][nf][e] = 0.f; im[mf][nf][e] = 0.f; }

        #pragma unroll
        for (int kp = 0; kp < 4; kp++) {
            uint32_t aR[2][4], aI[2][4], aRn[2][4];
            #pragma unroll
            for (int mf = 0; mf < 2; mf++) {
                int rowA = mrow0 + mf * 16 + rr;
                uint2 lo, hi;
                lo = *(const uint2*)(Ah + (kp * QT + rowA) * 16 + 4 * cc);
                hi = *(const uint2*)(Ah + (kp * QT + rowA + 8) * 16 + 4 * cc);
                aR[mf][0] = lo.x; aR[mf][1] = hi.x; aR[mf][2] = lo.y; aR[mf][3] = hi.y;
                lo = *(const uint2*)(Ah + ((kp + 4) * QT + rowA) * 16 + 4 * cc);
                hi = *(const uint2*)(Ah + ((kp + 4) * QT + rowA + 8) * 16 + 4 * cc);
                aI[mf][0] = lo.x; aI[mf][1] = hi.x; aI[mf][2] = lo.y; aI[mf][3] = hi.y;
                #pragma unroll
                for (int e = 0; e < 4; e++) aRn[mf][e] = aR[mf][e] ^ 0x80008000u;
            }
            uint2 bR[4], bI[4];
            #pragma unroll
            for (int nf = 0; nf < 4; nf++) {
                int keyB = warpn * 32 + nf * 8 + rr;
                bR[nf] = *(const uint2*)(Bh + (kp * KT + keyB) * 16 + 4 * cc);
                bI[nf] = *(const uint2*)(Bh + ((kp + 4) * KT + keyB) * 16 + 4 * cc);
            }
            #pragma unroll
            for (int mf = 0; mf < 2; mf++) {
                #pragma unroll
                for (int nf = 0; nf < 4; nf++) {
                    mma_f16(re[mf][nf], aR[mf][0], aR[mf][1], aR[mf][2], aR[mf][3],
                            bR[nf].x, bR[nf].y);
                    mma_f16(re[mf][nf], aI[mf][0], aI[mf][1], aI[mf][2], aI[mf][3],
                            bI[nf].x, bI[nf].y);
                    mma_f16(im[mf][nf], aI[mf][0], aI[mf][1], aI[mf][2], aI[mf][3],
                            bR[nf].x, bR[nf].y);
                    mma_f16(im[mf][nf], aRn[mf][0], aRn[mf][1], aRn[mf][2], aRn[mf][3],
                            bI[nf].x, bI[nf].y);
                }
            }
        }

        // ---- epilogue: w = exp(re^2+im^2) packed to fp16 -> P@V^T GEMM ----
        {
            const __half* Vb = Vh + buf * VS_HALVES;
            #pragma unroll
            for (int kch = 0; kch < 2; kch++) {
                int kbase = warpn * 32 + kch * 16;
                uint32_t b0 = *(const uint32_t*)(Vb + rr * VSTRIDE + kbase + 2 * cc);
                uint32_t b1 = *(const uint32_t*)(Vb + rr * VSTRIDE + kbase + 2 * cc + 8);
                #pragma unroll
                for (int mf = 0; mf < 2; mf++) {
                    int nlo = kch * 2, nhi = kch * 2 + 1;
                    float w[8];
                    #pragma unroll
                    for (int e = 0; e < 4; e++) {
                        float r = re[mf][nlo][e], i = im[mf][nlo][e];
                        w[e] = __expf(fmaf(r, r, i * i));
                        r = re[mf][nhi][e]; i = im[mf][nhi][e];
                        w[4 + e] = __expf(fmaf(r, r, i * i));
                    }
                    uint32_t a0 = packw(w[0], w[1]);
                    uint32_t a1 = packw(w[2], w[3]);
                    uint32_t a2 = packw(w[4], w[5]);
                    uint32_t a3 = packw(w[6], w[7]);
                    mma_f16(ovac[mf], a0, a1, a2, a3, b0, b1);
                }
            }
        }

        // ---- store prefetched tile into the other buffer ----
        if (has_next) {
            __half* Bn = (__half*)(smem + BH_OFF + (buf ^ 1) * BH_BYTES);
            #pragma unroll
            for (int i = 0; i < 8; i++) {
                int idx = tid + i * 256;
                int k = idx >> 5, j = idx & 31;
                uint2 v = kreg[i];
                uint32_t rep = __byte_perm(v.x, v.y, 0x5410);
                uint32_t imp = __byte_perm(v.x, v.y, 0x7632);
                int kk = j >> 3, p = kperm_pair(j & 7);
                *(uint32_t*)(Bn + (kk * KT + k) * 16 + p)       = rep;
                *(uint32_t*)(Bn + ((kk + 4) * KT + k) * 16 + p) = imp;
            }
            if (tid < 128)
                store_V(Vh + (buf ^ 1) * VS_HALVES, vreg, tid);
        }
        __syncthreads();

        // ---- qtile boundary: flush + reload A ----
        if (has_next && ((t + 1) >> 7) != qt) {
            flush(qt);
            qt = (t + 1) >> 7;
            load_A(qt);
            __syncthreads();
        }
    }
    flush(qt);
}

// ---------------------------------------------------------------------------
// Phase 3: deterministic combine — one warp per token; lanes 0..23 own slots.
// ---------------------------------------------------------------------------
__global__ void __launch_bounds__(256) finalize_kernel(float* __restrict__ out)
{
    int wid  = threadIdx.x >> 5;
    int lane = threadIdx.x & 31;
    int tok  = blockIdx.x * 8 + wid;
    if (tok >= NTOK) return;

    float num[6] = {0.f, 0.f, 0.f, 0.f, 0.f, 0.f};
    float den = 0.f;
    if (lane < NSLOT) {
        float4 a = *(const float4*)&g_part[tok][lane][0];
        float4 b = *(const float4*)&g_part[tok][lane][4];
        num[0] = a.x; num[1] = a.y; num[2] = a.z; num[3] = a.w;
        num[4] = b.x; num[5] = b.y; den = b.z;
    }
    #pragma unroll
    for (int off = 16; off >= 1; off >>= 1) {
        den += __shfl_xor_sync(0xffffffffu, den, off);
        #pragma unroll
        for (int c = 0; c < 6; c++)
            num[c] += __shfl_xor_sync(0xffffffffu, num[c], off);
    }
    if (lane == 0) {
        float inv = 1.f / den;
        #pragma unroll
        for (int c = 0; c < 6; c++) out[tok * 6 + c] = num[c] * inv;
    }
}

// ---------------------------------------------------------------------------
extern "C" void kernel_launch(void* const* d_in, const int* in_sizes, int n_in,
                              void* d_out, int out_size)
{
    const float* x  = (const float*)d_in[0];  // (8192, 6)
    const float* pq = (const float*)d_in[1];  // (2, 6, 2)
    const float* pk = (const float*)d_in[2];
    const float* pv = (const float*)d_in[3];
    float* out = (float*)d_out;               // (8192, 6) f32

    trig_kernel<<<1, 128>>>(pq, pk, pv);
    zero_kernel<<<(NTOK * NSLOT * 2 + 255) / 256, 256>>>();
    prep_kernel<<<(NTOK * 3) / 8, 256>>>(x);

    cudaFuncSetAttribute(attn_kernel, cudaFuncAttributeMaxDynamicSharedMemorySize, SMEM_BYTES);
    attn_kernel<<<NCTA, 256, SMEM_BYTES>>>();

    finalize_kernel<<<NTOK / 8, 256>>>(out);
}